// round 2
// baseline (speedup 1.0000x reference)
#include <cuda_runtime.h>

#define NN 2000
#define EE 32000
#define BB 8
#define TT 12
#define CIN 32
#define FCH 64
#define TBm 96        // T*B flattened "batch" dim
#define ROWLEN 3072   // TBm*CIN floats per node

typedef unsigned long long ull;

__device__ __forceinline__ void ffma2(ull &d, ull a, ull b) {
    asm("fma.rn.f32x2 %0, %1, %2, %0;" : "+l"(d) : "l"(a), "l"(b));
}
__device__ __forceinline__ ull pk(float x, float y) {
    float2 v = make_float2(x, y);
    return *reinterpret_cast<ull*>(&v);
}
__device__ __forceinline__ float2 upk(ull a) {
    return *reinterpret_cast<float2*>(&a);
}

// ---------------- scratch (static device globals; no allocation) ----------------
__device__ float g_x0[NN*ROWLEN];
__device__ float g_y1[NN*ROWLEN];
__device__ float g_z2[NN*ROWLEN];
__device__ float g_out[NN*TBm*FCH];
__device__ float g_deg[NN];
__device__ int   g_cnt[NN];
__device__ int   g_rowptr[NN+1];
__device__ int   g_cursor[NN];
__device__ float g_selfw[NN];
__device__ int   g_col[EE];
__device__ float g_wval[EE];

// ---------------- CSR build ----------------
__global__ void k_zero() {
    int i = blockIdx.x*blockDim.x + threadIdx.x;
    if (i < NN) { g_cnt[i] = 0; g_deg[i] = 0.f; }
}

__global__ void k_count(const int* __restrict__ ei, const float* __restrict__ ew) {
    int e = blockIdx.x*blockDim.x + threadIdx.x;
    if (e < EE) {
        atomicAdd(&g_cnt[ei[EE + e]], 1);       // in-degree count over dst
        atomicAdd(&g_deg[ei[e]], ew[e]);        // weighted degree over src (PyG)
    }
}

__global__ void k_scan(const float* __restrict__ lmax) {
    __shared__ int sa[2048], sb[2048];
    int tid = threadIdx.x;
    for (int i = tid; i < 2048; i += 1024) sa[i] = (i < NN) ? g_cnt[i] : 0;
    __syncthreads();
    int* src = sa; int* dst = sb;
    for (int off = 1; off < 2048; off <<= 1) {
        for (int i = tid; i < 2048; i += 1024)
            dst[i] = src[i] + ((i >= off) ? src[i - off] : 0);
        __syncthreads();
        int* tp = src; src = dst; dst = tp;
    }
    float alpha = 2.0f / lmax[0];
    for (int i = tid; i < NN; i += 1024) {
        g_rowptr[i+1] = src[i];
        g_cursor[i]   = (i == 0) ? 0 : src[i-1];
        g_selfw[i]    = alpha * g_deg[i] - 1.0f;   // appended self-loop: 2*deg/lmax - 1
    }
    if (tid == 0) g_rowptr[0] = 0;
}

__global__ void k_scatter(const int* __restrict__ ei, const float* __restrict__ ew,
                          const float* __restrict__ lmax) {
    int e = blockIdx.x*blockDim.x + threadIdx.x;
    if (e < EE) {
        int s = ei[e], d = ei[EE + e];
        int pos = atomicAdd(&g_cursor[d], 1);
        float alpha = 2.0f / lmax[0];
        g_col[pos]  = s;
        g_wval[pos] = -alpha * ew[e] - ((s == d) ? 1.0f : 0.0f);
    }
}

// ---------------- x0 materialization (faithful buggy permute+reshape) ----------------
__global__ void k_x0(const float* __restrict__ X) {
    __shared__ float s[32*97];
    int n2 = blockIdx.x;
    int tid = threadIdx.x;
    for (int i = tid; i < ROWLEN; i += 256) {
        int u = n2*ROWLEN + i;
        int c   = u / 192000;       int rem  = u - c*192000;
        int b   = rem / 24000;      int rem2 = rem - b*24000;
        int n   = rem2 / 12;        int t    = rem2 - n*12;
        int c2 = i / 96, m = i - c2*96;
        s[c2*97 + m] = X[((b*NN + n)*CIN + c)*TT + t];
    }
    __syncthreads();
    for (int i = tid; i < ROWLEN; i += 256) {
        int m = i >> 5, c2 = i & 31;
        g_x0[n2*ROWLEN + i] = s[c2*97 + m];
    }
}

// ---------------- graph propagation (CSR gather, float4, no atomics) ----------------
__global__ void k_prop(int mode) {
    const float4* in  = (const float4*)((mode == 1) ? g_x0 : g_y1);
    float4*       out = (float4*)((mode == 1) ? g_y1 : g_z2);
    int n = blockIdx.x;
    int f = threadIdx.x;                 // float4 lanes: f, f+256, f+512 (768 per row)
    int beg = g_rowptr[n], end = g_rowptr[n+1];
    float sw = g_selfw[n];
    const float4* r = in + (size_t)n*768;
    float4 r0 = r[f], r1 = r[f+256], r2 = r[f+512];
    float4 a0, a1, a2;
    a0.x=sw*r0.x; a0.y=sw*r0.y; a0.z=sw*r0.z; a0.w=sw*r0.w;
    a1.x=sw*r1.x; a1.y=sw*r1.y; a1.z=sw*r1.z; a1.w=sw*r1.w;
    a2.x=sw*r2.x; a2.y=sw*r2.y; a2.z=sw*r2.z; a2.w=sw*r2.w;
    for (int e = beg; e < end; e++) {
        int s = g_col[e]; float w = g_wval[e];
        const float4* rs = in + (size_t)s*768;
        float4 v0 = rs[f], v1 = rs[f+256], v2 = rs[f+512];
        a0.x+=w*v0.x; a0.y+=w*v0.y; a0.z+=w*v0.z; a0.w+=w*v0.w;
        a1.x+=w*v1.x; a1.y+=w*v1.y; a1.z+=w*v1.z; a1.w+=w*v1.w;
        a2.x+=w*v2.x; a2.y+=w*v2.y; a2.z+=w*v2.z; a2.w+=w*v2.w;
    }
    size_t o = (size_t)n*768 + f;
    if (mode == 1) {
        out[o] = a0; out[o+256] = a1; out[o+512] = a2;
    } else {
        const float4* x0p = (const float4*)g_x0;
        float4 b0 = x0p[o], b1 = x0p[o+256], b2 = x0p[o+512];
        float4 w0, w1, w2;
        w0.x=2.f*a0.x-b0.x; w0.y=2.f*a0.y-b0.y; w0.z=2.f*a0.z-b0.z; w0.w=2.f*a0.w-b0.w;
        w1.x=2.f*a1.x-b1.x; w1.y=2.f*a1.y-b1.y; w1.z=2.f*a1.z-b1.z; w1.w=2.f*a1.w-b1.w;
        w2.x=2.f*a2.x-b2.x; w2.y=2.f*a2.y-b2.y; w2.z=2.f*a2.z-b2.z; w2.w=2.f*a2.w-b2.w;
        out[o] = w0; out[o+256] = w1; out[o+512] = w2;
    }
}

// ---------------- Chebyshev contraction: out = relu([x0|y1|z2] @ Wcheb + b) ----------
// f32x2 packed along rows. Tile: 128 rows x 64 f, 256 threads, 8 rows x 4 f per thread.
#define AST 130   // As_t row stride (floats)
__global__ void k_gemm(const float* __restrict__ wcheb, const float* __restrict__ bcheb) {
    extern __shared__ float sm[];
    float* As_t = sm;               // [96][AST] transposed A: As_t[c*AST + r]
    float* Wd   = sm + 96*AST;      // [96][128] duplicated weights: Wd[c*128 + 2f{,+1}]
    int row0 = blockIdx.x * 128;
    int tid = threadIdx.x;

    for (int i = tid; i < 128*96; i += 256) {
        int r = i / 96, c = i - r*96;
        const float* src = (c < 32) ? g_x0 : ((c < 64) ? g_y1 : g_z2);
        As_t[c*AST + r] = src[(size_t)(row0 + r)*32 + (c & 31)];
    }
    for (int i = tid; i < 96*64; i += 256) {
        int c = i >> 6, f = i & 63;
        float w = wcheb[i];
        *reinterpret_cast<float2*>(&Wd[c*128 + 2*f]) = make_float2(w, w);
    }
    __syncthreads();

    int tx = tid & 15, ty = tid >> 4;   // f0 = tx*4, r0 = ty*8
    int f0 = tx*4, r0 = ty*8;
    ull acc[4][4];
    #pragma unroll
    for (int f = 0; f < 4; f++)
        #pragma unroll
        for (int p = 0; p < 4; p++) acc[f][p] = 0ull;

    #pragma unroll 4
    for (int c = 0; c < 96; c++) {
        const ull* ap = reinterpret_cast<const ull*>(&As_t[c*AST + r0]);
        ull a0 = ap[0], a1 = ap[1], a2 = ap[2], a3 = ap[3];
        const ull* wp = reinterpret_cast<const ull*>(&Wd[c*128 + 2*f0]);
        ull w0 = wp[0], w1 = wp[1], w2 = wp[2], w3 = wp[3];
        ffma2(acc[0][0], w0, a0); ffma2(acc[0][1], w0, a1); ffma2(acc[0][2], w0, a2); ffma2(acc[0][3], w0, a3);
        ffma2(acc[1][0], w1, a0); ffma2(acc[1][1], w1, a1); ffma2(acc[1][2], w1, a2); ffma2(acc[1][3], w1, a3);
        ffma2(acc[2][0], w2, a0); ffma2(acc[2][1], w2, a1); ffma2(acc[2][2], w2, a2); ffma2(acc[2][3], w2, a3);
        ffma2(acc[3][0], w3, a0); ffma2(acc[3][1], w3, a1); ffma2(acc[3][2], w3, a2); ffma2(acc[3][3], w3, a3);
    }

    const float4 bb4 = *reinterpret_cast<const float4*>(&bcheb[f0]);
    #pragma unroll
    for (int p = 0; p < 4; p++) {
        float2 v0 = upk(acc[0][p]), v1 = upk(acc[1][p]), v2 = upk(acc[2][p]), v3 = upk(acc[3][p]);
        float4 oA, oB;
        oA.x = fmaxf(v0.x + bb4.x, 0.f); oA.y = fmaxf(v1.x + bb4.y, 0.f);
        oA.z = fmaxf(v2.x + bb4.z, 0.f); oA.w = fmaxf(v3.x + bb4.w, 0.f);
        oB.x = fmaxf(v0.y + bb4.x, 0.f); oB.y = fmaxf(v1.y + bb4.y, 0.f);
        oB.z = fmaxf(v2.y + bb4.z, 0.f); oB.w = fmaxf(v3.y + bb4.w, 0.f);
        int row = row0 + r0 + 2*p;
        *reinterpret_cast<float4*>(&g_out[(size_t)row*64 + f0])     = oA;
        *reinterpret_cast<float4*>(&g_out[(size_t)(row+1)*64 + f0]) = oB;
    }
}

// ---------------- fused temporal conv + residual + relu + LayerNorm + output ------
// f32x2 packed along f. block = (b, 8 nodes), 256 threads: thread = (fp = tid&31, ng = tid>>5)
// SMEM (ull units):
//   xdup  [8][64][12]  @0      (6144)   x dup'd per value   (aliased later as zb floats)
//   xsdup [8][32][12]  @6144   (3072)
//   twp   [64][3][32]  @9216   (6144)   f-pair packed temporal weights
//   rwp   [32][32]     @15360  (1024)
//   biasp [32]         @16384  (32)     tb+rb f-pair packed
//   floats @16416: lg[64], lb[64], mu[96], rs[96]
#define EPI_SMEM (16576*8)
__global__ void k_epi(const float* __restrict__ X,  const float* __restrict__ tw,
                      const float* __restrict__ tb, const float* __restrict__ rw,
                      const float* __restrict__ rb, const float* __restrict__ lg,
                      const float* __restrict__ lb, float* __restrict__ O) {
    extern __shared__ ull smu[];
    ull* xdup  = smu;
    ull* xsdup = smu + 6144;
    ull* twp   = smu + 9216;
    ull* rwp   = smu + 15360;
    ull* biasp = smu + 16384;
    float* aux = (float*)(smu + 16416);
    float* lg_s = aux;         float* lb_s = aux + 64;
    float* mu_s = aux + 128;   float* rs_s = aux + 224;

    int b  = blockIdx.y;
    int n0 = blockIdx.x * 8;
    int tid = threadIdx.x;

    // fill xdup: [ng][fc][t] = dup(g_out[((n0+ng)*96 + b*12 + t)*64 + fc])
    for (int i = tid; i < 8*768; i += 256) {
        int ng = i >> 9 | 0; ng = i / 768; int j = i - ng*768;
        int t = j >> 6, fc = j & 63;
        float v = g_out[((size_t)(n0 + ng)*TBm + b*TT + t)*64 + fc];
        xdup[ng*768 + fc*12 + t] = pk(v, v);
    }
    // fill xsdup: [ng][c][t] = dup(X[b, n0+ng, c, t])
    for (int i = tid; i < 8*384; i += 256) {
        int ng = i / 384; int j = i - ng*384;
        float v = X[((size_t)(b*NN + n0 + ng)*CIN)*TT + j];
        xsdup[i] = pk(v, v);
    }
    // twp[fc][j][fp] = (tw[2fp][fc][j], tw[2fp+1][fc][j])
    for (int i = tid; i < 64*96; i += 256) {
        int fc = i / 96; int q = i - fc*96;
        int j = q >> 5, fp = q & 31;
        twp[i] = pk(tw[(2*fp)*192 + fc*3 + j], tw[(2*fp+1)*192 + fc*3 + j]);
    }
    // rwp[c][fp]
    for (int i = tid; i < 32*32; i += 256) {
        int c = i >> 5, fp = i & 31;
        rwp[i] = pk(rw[(2*fp)*32 + c], rw[(2*fp+1)*32 + c]);
    }
    if (tid < 32) biasp[tid] = pk(tb[2*tid] + rb[2*tid], tb[2*tid+1] + rb[2*tid+1]);
    if (tid < 64) { lg_s[tid] = lg[tid]; lb_s[tid] = lb[tid]; }
    __syncthreads();

    int fp = tid & 31, ng = tid >> 5;
    ull acc[12];
    {
        ull binit = biasp[fp];
        #pragma unroll
        for (int t = 0; t < 12; t++) acc[t] = binit;
    }

    // temporal 1x3 conv (pad 1)
    const ulonglong2* xd = reinterpret_cast<const ulonglong2*>(xdup + ng*768);
    #pragma unroll 4
    for (int fc = 0; fc < 64; fc++) {
        ull w0 = twp[fc*96 + fp], w1 = twp[fc*96 + 32 + fp], w2 = twp[fc*96 + 64 + fp];
        ulonglong2 p0 = xd[fc*6+0], p1 = xd[fc*6+1], p2 = xd[fc*6+2];
        ulonglong2 p3 = xd[fc*6+3], p4 = xd[fc*6+4], p5 = xd[fc*6+5];
        ull d[12] = {p0.x,p0.y,p1.x,p1.y,p2.x,p2.y,p3.x,p3.y,p4.x,p4.y,p5.x,p5.y};
        #pragma unroll
        for (int t = 0; t < 12; t++) {
            ffma2(acc[t], d[t], w1);
            if (t < 11) ffma2(acc[t+1], d[t], w0);
            if (t > 0)  ffma2(acc[t-1], d[t], w2);
        }
    }
    // 1x1 residual conv on raw X
    const ulonglong2* xs2 = reinterpret_cast<const ulonglong2*>(xsdup + ng*384);
    #pragma unroll 4
    for (int c = 0; c < 32; c++) {
        ull rwv = rwp[c*32 + fp];
        ulonglong2 p0 = xs2[c*6+0], p1 = xs2[c*6+1], p2 = xs2[c*6+2];
        ulonglong2 p3 = xs2[c*6+3], p4 = xs2[c*6+4], p5 = xs2[c*6+5];
        ull d[12] = {p0.x,p0.y,p1.x,p1.y,p2.x,p2.y,p3.x,p3.y,p4.x,p4.y,p5.x,p5.y};
        #pragma unroll
        for (int t = 0; t < 12; t++) ffma2(acc[t], d[t], rwv);
    }
    __syncthreads();        // all xdup reads done -> safe to alias as zb
    float* zb = (float*)xdup;
    #pragma unroll
    for (int t = 0; t < 12; t++) {
        float2 v = upk(acc[t]);
        *reinterpret_cast<float2*>(&zb[(ng*12 + t)*64 + 2*fp]) =
            make_float2(fmaxf(v.x, 0.f), fmaxf(v.y, 0.f));
    }
    __syncthreads();

    // LayerNorm over f per (ng, t): 8 warps x 12 rows = 96 rows
    int wid = tid >> 5, lane = tid & 31;
    for (int k = 0; k < 12; k++) {
        int row = wid*12 + k;
        float v1 = zb[row*64 + lane];
        float v2 = zb[row*64 + 32 + lane];
        float s = v1 + v2, q = v1*v1 + v2*v2;
        #pragma unroll
        for (int o = 16; o > 0; o >>= 1) {
            s += __shfl_xor_sync(0xffffffffu, s, o);
            q += __shfl_xor_sync(0xffffffffu, q, o);
        }
        if (lane == 0) {
            float mu  = s * (1.f/64.f);
            float var = q * (1.f/64.f) - mu*mu;
            mu_s[row] = mu;
            rs_s[row] = rsqrtf(var + 1e-5f);
        }
    }
    __syncthreads();

    // output O[b, n, f, t] — coalesced 768-float block per node
    for (int i = tid; i < 8*768; i += 256) {
        int ng2 = i / 768; int j = i - ng2*768;
        int fo = j / 12, to = j - fo*12;
        float z  = zb[(ng2*12 + to)*64 + fo];
        float mu = mu_s[ng2*12 + to], rs = rs_s[ng2*12 + to];
        O[((size_t)(b*NN + n0 + ng2))*768 + j] = (z - mu)*rs*lg_s[fo] + lb_s[fo];
    }
}

// ---------------- launch ----------------
extern "C" void kernel_launch(void* const* d_in, const int* in_sizes, int n_in,
                              void* d_out, int out_size) {
    const float* X     = (const float*)d_in[0];
    const int*   ei    = (const int*)  d_in[1];
    const float* ew    = (const float*)d_in[2];
    const float* lmax  = (const float*)d_in[3];
    const float* wcheb = (const float*)d_in[4];
    const float* bcheb = (const float*)d_in[5];
    const float* tw    = (const float*)d_in[6];
    const float* tb    = (const float*)d_in[7];
    const float* rw    = (const float*)d_in[8];
    const float* rb    = (const float*)d_in[9];
    const float* lng   = (const float*)d_in[10];
    const float* lnb   = (const float*)d_in[11];
    float* O = (float*)d_out;

    int gemm_smem = (96*AST + 96*128) * 4;   // 99072
    cudaFuncSetAttribute(k_gemm, cudaFuncAttributeMaxDynamicSharedMemorySize, gemm_smem);
    cudaFuncSetAttribute(k_epi,  cudaFuncAttributeMaxDynamicSharedMemorySize, EPI_SMEM);

    k_zero   <<<8,   256>>>();
    k_count  <<<125, 256>>>(ei, ew);
    k_scan   <<<1,  1024>>>(lmax);
    k_scatter<<<125, 256>>>(ei, ew, lmax);
    k_x0     <<<2000,256>>>(X);
    k_prop   <<<2000,256>>>(1);
    k_prop   <<<2000,256>>>(2);
    k_gemm   <<<1500,256,gemm_smem>>>(wcheb, bcheb);
    k_epi    <<<dim3(250,8),256,EPI_SMEM>>>(X, tw, tb, rw, rb, lng, lnb, O);
}

// round 3
// speedup vs baseline: 1.5930x; 1.5930x over previous
#include <cuda_runtime.h>

#define NN 2000
#define EE 32000
#define BB 8
#define TT 12
#define CIN 32
#define FCH 64
#define TBm 96        // T*B flattened "batch" dim
#define ROWLEN 3072   // TBm*CIN floats per node

typedef unsigned long long ull;

__device__ __forceinline__ void ffma2(ull &d, ull a, ull b) {
    asm("fma.rn.f32x2 %0, %1, %2, %0;" : "+l"(d) : "l"(a), "l"(b));
}
__device__ __forceinline__ ull pk(float x, float y) {
    float2 v = make_float2(x, y);
    return *reinterpret_cast<ull*>(&v);
}
__device__ __forceinline__ ull splat(float x) {
    ull r;
    asm("mov.b64 %0, {%1, %1};" : "=l"(r) : "f"(x));
    return r;
}
__device__ __forceinline__ float2 upk(ull a) {
    return *reinterpret_cast<float2*>(&a);
}

// ---------------- scratch (static device globals; no allocation) ----------------
__device__ float g_x0[NN*ROWLEN];
__device__ float g_y1[NN*ROWLEN];
__device__ float g_z2[NN*ROWLEN];
__device__ float g_out[NN*TBm*FCH];
__device__ float g_deg[NN];
__device__ int   g_cnt[NN];
__device__ int   g_rowptr[NN+1];
__device__ int   g_cursor[NN];
__device__ float g_selfw[NN];
__device__ int   g_col[EE];
__device__ float g_wval[EE];

// ---------------- CSR build ----------------
__global__ void k_zero() {
    int i = blockIdx.x*blockDim.x + threadIdx.x;
    if (i < NN) { g_cnt[i] = 0; g_deg[i] = 0.f; }
}

__global__ void k_count(const int* __restrict__ ei, const float* __restrict__ ew) {
    int e = blockIdx.x*blockDim.x + threadIdx.x;
    if (e < EE) {
        atomicAdd(&g_cnt[ei[EE + e]], 1);       // in-degree count over dst
        atomicAdd(&g_deg[ei[e]], ew[e]);        // weighted degree over src (PyG)
    }
}

__global__ void k_scan(const float* __restrict__ lmax) {
    __shared__ int sa[2048], sb[2048];
    int tid = threadIdx.x;
    for (int i = tid; i < 2048; i += 1024) sa[i] = (i < NN) ? g_cnt[i] : 0;
    __syncthreads();
    int* src = sa; int* dst = sb;
    for (int off = 1; off < 2048; off <<= 1) {
        for (int i = tid; i < 2048; i += 1024)
            dst[i] = src[i] + ((i >= off) ? src[i - off] : 0);
        __syncthreads();
        int* tp = src; src = dst; dst = tp;
    }
    float alpha = 2.0f / lmax[0];
    for (int i = tid; i < NN; i += 1024) {
        g_rowptr[i+1] = src[i];
        g_cursor[i]   = (i == 0) ? 0 : src[i-1];
        g_selfw[i]    = alpha * g_deg[i] - 1.0f;   // appended self-loop: 2*deg/lmax - 1
    }
    if (tid == 0) g_rowptr[0] = 0;
}

__global__ void k_scatter(const int* __restrict__ ei, const float* __restrict__ ew,
                          const float* __restrict__ lmax) {
    int e = blockIdx.x*blockDim.x + threadIdx.x;
    if (e < EE) {
        int s = ei[e], d = ei[EE + e];
        int pos = atomicAdd(&g_cursor[d], 1);
        float alpha = 2.0f / lmax[0];
        g_col[pos]  = s;
        g_wval[pos] = -alpha * ew[e] - ((s == d) ? 1.0f : 0.0f);
    }
}

// ---------------- x0 materialization (faithful buggy permute+reshape) ----------------
__global__ void k_x0(const float* __restrict__ X) {
    __shared__ float s[32*97];
    int n2 = blockIdx.x;
    int tid = threadIdx.x;
    for (int i = tid; i < ROWLEN; i += 256) {
        int u = n2*ROWLEN + i;
        int c   = u / 192000;       int rem  = u - c*192000;
        int b   = rem / 24000;      int rem2 = rem - b*24000;
        int n   = rem2 / 12;        int t    = rem2 - n*12;
        int c2 = i / 96, m = i - c2*96;
        s[c2*97 + m] = X[((b*NN + n)*CIN + c)*TT + t];
    }
    __syncthreads();
    for (int i = tid; i < ROWLEN; i += 256) {
        int m = i >> 5, c2 = i & 31;
        g_x0[n2*ROWLEN + i] = s[c2*97 + m];
    }
}

// ---------------- graph propagation (CSR gather, no atomics) — round-1 form ------
__global__ void k_prop(int mode) {
    const float* in  = (mode == 1) ? g_x0 : g_y1;
    float*       out = (mode == 1) ? g_y1 : g_z2;
    int n = blockIdx.y;
    int f = blockIdx.x*768 + threadIdx.x;
    int beg = g_rowptr[n], end = g_rowptr[n+1];
    float sw = g_selfw[n];
    const float* r = in + (size_t)n*ROWLEN;
    float a0 = sw*r[f], a1 = sw*r[f+256], a2 = sw*r[f+512];
    for (int e = beg; e < end; e++) {
        int s = g_col[e]; float w = g_wval[e];
        const float* rs = in + (size_t)s*ROWLEN;
        a0 += w*rs[f]; a1 += w*rs[f+256]; a2 += w*rs[f+512];
    }
    size_t o = (size_t)n*ROWLEN + f;
    if (mode == 1) {
        out[o] = a0; out[o+256] = a1; out[o+512] = a2;
    } else {
        out[o]     = 2.f*a0 - g_x0[o];
        out[o+256] = 2.f*a1 - g_x0[o+256];
        out[o+512] = 2.f*a2 - g_x0[o+512];
    }
}

// ---------------- Chebyshev contraction: out = relu([x0|y1|z2] @ Wcheb + b) ----------
// f32x2 packed along rows; W scalar in SMEM + per-thread splat.
// Tile: 128 rows x 64 f, 256 threads, 8 rows x 4 f per thread.
#define AST 130   // As_t row stride (floats)
#define GEMM_SMEM ((96*AST + 96*64) * 4)
__global__ __launch_bounds__(256, 3)
void k_gemm(const float* __restrict__ wcheb, const float* __restrict__ bcheb) {
    extern __shared__ float sm[];
    float* As_t = sm;               // [96][AST] transposed A: As_t[c*AST + r]
    float* Ws   = sm + 96*AST;      // [96][64] scalar weights
    int row0 = blockIdx.x * 128;
    int tid = threadIdx.x;

    for (int i = tid; i < 128*96; i += 256) {
        int r = i / 96, c = i - r*96;
        const float* src = (c < 32) ? g_x0 : ((c < 64) ? g_y1 : g_z2);
        As_t[c*AST + r] = src[(size_t)(row0 + r)*32 + (c & 31)];
    }
    for (int i = tid; i < 96*64; i += 256) Ws[i] = wcheb[i];
    __syncthreads();

    int tx = tid & 15, ty = tid >> 4;
    int f0 = tx*4, r0 = ty*8;
    ull acc[4][4];
    #pragma unroll
    for (int f = 0; f < 4; f++)
        #pragma unroll
        for (int p = 0; p < 4; p++) acc[f][p] = 0ull;

    #pragma unroll 4
    for (int c = 0; c < 96; c++) {
        const ull* ap = reinterpret_cast<const ull*>(&As_t[c*AST + r0]);
        ull a0 = ap[0], a1 = ap[1], a2 = ap[2], a3 = ap[3];
        float4 wv = *reinterpret_cast<const float4*>(&Ws[c*64 + f0]);
        ull w0 = splat(wv.x), w1 = splat(wv.y), w2 = splat(wv.z), w3 = splat(wv.w);
        ffma2(acc[0][0], w0, a0); ffma2(acc[0][1], w0, a1); ffma2(acc[0][2], w0, a2); ffma2(acc[0][3], w0, a3);
        ffma2(acc[1][0], w1, a0); ffma2(acc[1][1], w1, a1); ffma2(acc[1][2], w1, a2); ffma2(acc[1][3], w1, a3);
        ffma2(acc[2][0], w2, a0); ffma2(acc[2][1], w2, a1); ffma2(acc[2][2], w2, a2); ffma2(acc[2][3], w2, a3);
        ffma2(acc[3][0], w3, a0); ffma2(acc[3][1], w3, a1); ffma2(acc[3][2], w3, a2); ffma2(acc[3][3], w3, a3);
    }

    const float4 bb4 = *reinterpret_cast<const float4*>(&bcheb[f0]);
    #pragma unroll
    for (int p = 0; p < 4; p++) {
        float2 v0 = upk(acc[0][p]), v1 = upk(acc[1][p]), v2 = upk(acc[2][p]), v3 = upk(acc[3][p]);
        float4 oA, oB;
        oA.x = fmaxf(v0.x + bb4.x, 0.f); oA.y = fmaxf(v1.x + bb4.y, 0.f);
        oA.z = fmaxf(v2.x + bb4.z, 0.f); oA.w = fmaxf(v3.x + bb4.w, 0.f);
        oB.x = fmaxf(v0.y + bb4.x, 0.f); oB.y = fmaxf(v1.y + bb4.y, 0.f);
        oB.z = fmaxf(v2.y + bb4.z, 0.f); oB.w = fmaxf(v3.y + bb4.w, 0.f);
        int row = row0 + r0 + 2*p;
        *reinterpret_cast<float4*>(&g_out[(size_t)row*64 + f0])     = oA;
        *reinterpret_cast<float4*>(&g_out[(size_t)(row+1)*64 + f0]) = oB;
    }
}

// ---------------- fused temporal conv + residual + relu + LayerNorm + output ------
// f32x2 packed along NODE PAIRS (no data duplication). block = (b, 8 nodes),
// 256 threads: thread = (f = tid&63, pr = tid>>6) where pr = node pair (0..3).
// SMEM (bytes):
//   xp  [64 fc][stride 50 ull] : pairs (nA,nB) per (fc,t)      25600  (aliased as zb)
//   xsp [32 c ][stride 50 ull] : raw-X pairs                   12800
//   tws [192 rows][stride 65 f]: scalar temporal weights       49920
//   rws [32 c][stride 65 f]    : scalar residual weights        8320
//   tbrb/lg/lb [64]x3, mu/rs [96]x2                             1536
#define XP_ST  50
#define EPI_SMEM (25600 + 12800 + 49920 + 8320 + 1536)
__global__ __launch_bounds__(256, 2)
void k_epi(const float* __restrict__ X,  const float* __restrict__ tw,
           const float* __restrict__ tb, const float* __restrict__ rw,
           const float* __restrict__ rb, const float* __restrict__ lg,
           const float* __restrict__ lb, float* __restrict__ O) {
    extern __shared__ ull smu[];
    ull* xp  = smu;                       // 3200 ull
    ull* xsp = smu + 3200;                // 1600 ull
    float* tws  = (float*)(smu + 4800);   // 12480 floats
    float* rws  = tws + 12480;            // 2080 floats
    float* tbrb = rws + 2080;             // 64
    float* lg_s = tbrb + 64;              // 64
    float* lb_s = lg_s + 64;              // 64
    float* mu_s = lb_s + 64;              // 96
    float* rs_s = mu_s + 96;              // 96

    int b  = blockIdx.y;
    int n0 = blockIdx.x * 8;
    int tid = threadIdx.x;

    // xp fill: pair (n0+2pr, n0+2pr+1) values of Xc[fc][t]; coalesced g_out reads
    float* xpf = (float*)xp;
    for (int i = tid; i < 6144; i += 256) {
        int fc = i & 63, v = i >> 6;          // v = nloc*12 + t
        int nloc = v / 12, t = v - nloc*12;
        float val = g_out[((size_t)(n0 + nloc)*TBm + b*TT + t)*64 + fc];
        int pr = nloc >> 1, half = nloc & 1;
        xpf[(fc*XP_ST + pr*12 + t)*2 + half] = val;
    }
    // xsp fill: raw X pairs; coalesced X reads
    float* xspf = (float*)xsp;
    for (int i = tid; i < 3072; i += 256) {
        int nloc = i / 384, r = i - nloc*384;  // r = c*12 + t
        int c = r / 12, t = r - c*12;
        float val = X[((size_t)(b*NN + n0 + nloc)*CIN)*TT + r];
        int pr = nloc >> 1, half = nloc & 1;
        xspf[(c*XP_ST + pr*12 + t)*2 + half] = val;
    }
    // tws[q*65 + f] = tw[f*192 + q]  (coalesced read, pad-65 conflict-free write)
    for (int i = tid; i < 64*192; i += 256) {
        int f = i / 192, q = i - f*192;
        tws[q*65 + f] = tw[i];
    }
    // rws[c*65 + f] = rw[f*32 + c]
    for (int i = tid; i < 64*32; i += 256) {
        int f = i >> 5, c = i & 31;
        rws[c*65 + f] = rw[i];
    }
    if (tid < 64) { tbrb[tid] = tb[tid] + rb[tid]; lg_s[tid] = lg[tid]; lb_s[tid] = lb[tid]; }
    __syncthreads();

    int f = tid & 63, pr = tid >> 6;
    ull acc[12];
    {
        ull binit = splat(tbrb[f]);
        #pragma unroll
        for (int t = 0; t < 12; t++) acc[t] = binit;
    }

    // temporal 1x3 conv (pad 1) — x pairs broadcast across the warp
    #pragma unroll 4
    for (int fc = 0; fc < 64; fc++) {
        const ulonglong2* xr = reinterpret_cast<const ulonglong2*>(xp + fc*XP_ST + pr*12);
        ulonglong2 q0 = xr[0], q1 = xr[1], q2 = xr[2], q3 = xr[3], q4 = xr[4], q5 = xr[5];
        ull d[12] = {q0.x,q0.y,q1.x,q1.y,q2.x,q2.y,q3.x,q3.y,q4.x,q4.y,q5.x,q5.y};
        ull w0 = splat(tws[(fc*3+0)*65 + f]);
        ull w1 = splat(tws[(fc*3+1)*65 + f]);
        ull w2 = splat(tws[(fc*3+2)*65 + f]);
        #pragma unroll
        for (int t = 0; t < 12; t++) {
            ffma2(acc[t], d[t], w1);
            if (t < 11) ffma2(acc[t+1], d[t], w0);
            if (t > 0)  ffma2(acc[t-1], d[t], w2);
        }
    }
    // 1x1 residual conv on raw X
    #pragma unroll 4
    for (int c = 0; c < 32; c++) {
        const ulonglong2* xr = reinterpret_cast<const ulonglong2*>(xsp + c*XP_ST + pr*12);
        ulonglong2 q0 = xr[0], q1 = xr[1], q2 = xr[2], q3 = xr[3], q4 = xr[4], q5 = xr[5];
        ull d[12] = {q0.x,q0.y,q1.x,q1.y,q2.x,q2.y,q3.x,q3.y,q4.x,q4.y,q5.x,q5.y};
        ull rwv = splat(rws[c*65 + f]);
        #pragma unroll
        for (int t = 0; t < 12; t++) ffma2(acc[t], d[t], rwv);
    }
    __syncthreads();            // xp reads done -> alias as zb
    float* zb = (float*)xp;     // [8 n][12 t][64 f]
    #pragma unroll
    for (int t = 0; t < 12; t++) {
        float2 v = upk(acc[t]);
        zb[((2*pr)*12 + t)*64 + f]   = fmaxf(v.x, 0.f);
        zb[((2*pr+1)*12 + t)*64 + f] = fmaxf(v.y, 0.f);
    }
    __syncthreads();

    // LayerNorm over f per (node, t): 8 warps x 12 rows = 96 rows
    int wid = tid >> 5, lane = tid & 31;
    for (int k = 0; k < 12; k++) {
        int row = wid*12 + k;
        float v1 = zb[row*64 + lane];
        float v2 = zb[row*64 + 32 + lane];
        float s = v1 + v2, q = v1*v1 + v2*v2;
        #pragma unroll
        for (int o = 16; o > 0; o >>= 1) {
            s += __shfl_xor_sync(0xffffffffu, s, o);
            q += __shfl_xor_sync(0xffffffffu, q, o);
        }
        if (lane == 0) {
            float mu  = s * (1.f/64.f);
            float var = q * (1.f/64.f) - mu*mu;
            mu_s[row] = mu;
            rs_s[row] = rsqrtf(var + 1e-5f);
        }
    }
    __syncthreads();

    // output O[b, n, f, t] — coalesced 768-float block per node
    for (int i = tid; i < 8*768; i += 256) {
        int ng = i / 768, j = i - ng*768;
        int fo = j / 12, to = j - fo*12;
        float z  = zb[(ng*12 + to)*64 + fo];
        float mu = mu_s[ng*12 + to], rs = rs_s[ng*12 + to];
        O[((size_t)(b*NN + n0 + ng))*768 + j] = (z - mu)*rs*lg_s[fo] + lb_s[fo];
    }
}

// ---------------- launch ----------------
extern "C" void kernel_launch(void* const* d_in, const int* in_sizes, int n_in,
                              void* d_out, int out_size) {
    const float* X     = (const float*)d_in[0];
    const int*   ei    = (const int*)  d_in[1];
    const float* ew    = (const float*)d_in[2];
    const float* lmax  = (const float*)d_in[3];
    const float* wcheb = (const float*)d_in[4];
    const float* bcheb = (const float*)d_in[5];
    const float* tw    = (const float*)d_in[6];
    const float* tb    = (const float*)d_in[7];
    const float* rw    = (const float*)d_in[8];
    const float* rb    = (const float*)d_in[9];
    const float* lng   = (const float*)d_in[10];
    const float* lnb   = (const float*)d_in[11];
    float* O = (float*)d_out;

    cudaFuncSetAttribute(k_gemm, cudaFuncAttributeMaxDynamicSharedMemorySize, GEMM_SMEM);
    cudaFuncSetAttribute(k_epi,  cudaFuncAttributeMaxDynamicSharedMemorySize, EPI_SMEM);

    k_zero   <<<8,   256>>>();
    k_count  <<<125, 256>>>(ei, ew);
    k_scan   <<<1,  1024>>>(lmax);
    k_scatter<<<125, 256>>>(ei, ew, lmax);
    k_x0     <<<2000,256>>>(X);
    k_prop   <<<dim3(4,2000),256>>>(1);
    k_prop   <<<dim3(4,2000),256>>>(2);
    k_gemm   <<<1500,256,GEMM_SMEM>>>(wcheb, bcheb);
    k_epi    <<<dim3(250,8),256,EPI_SMEM>>>(X, tw, tb, rw, rb, lng, lnb, O);
}